// round 15
// baseline (speedup 1.0000x reference)
#include <cuda_runtime.h>
#include <cuda_fp16.h>
#include <cuda_bf16.h>

// ---------------------------------------------------------------------------
// GATv2-like layer, factorized global softmax + CSR edge aggregation.
//   h = x @ W^T ; scores separable => w[e,h] = es[src,h]*ed[dst,h]/Z_h
//   p[n] = es[n]*h[n]  (fp16, pre-scaled gather payload)
//   out[d] = ed[d]*invZ * ( p[d] + sum_{in-edges} p[s] ) + bias
// Pipeline (7 launches):
//   prep -> gemm_fused(f32x2 FFMA2, writes p fp16 + es/ed + Z-self)
//   -> histz -> scan1 -> scan3(+invZ) -> scatter -> edgeacc(+scale+bias)
// ---------------------------------------------------------------------------

#define IN_F      128
#define HEADS     4
#define OUT_F     32
#define HF        128
#define NEG_SLOPE 0.2f
#define MAX_NODES 50000
#define MAX_EDGES 800000

typedef unsigned long long ull;

__device__ __half g_p[MAX_NODES * HF];       // 12.8 MB, es-prescaled h (fp16)
__device__ float  g_Wt[IN_F * HF];           // W^T, k-major
__device__ float  g_es[MAX_NODES * HEADS];
__device__ float  g_ed[MAX_NODES * HEADS];
__device__ float  g_Z[HEADS];
__device__ float  g_invZ[HEADS];
__device__ int    g_is64;

__device__ int    g_deg[MAX_NODES];
__device__ int    g_off[MAX_NODES + 1];
__device__ int    g_bsum[64];
__device__ int    g_rank[MAX_EDGES];
__device__ int    g_srcidx[MAX_EDGES];

// packed f32x2 FMA: d.lo += a.lo*b.lo ; d.hi += a.hi*b.hi
#define FFMA2(d, a, b) \
    asm("fma.rn.f32x2 %0, %1, %2, %0;" : "+l"(d) : "l"(a), "l"(b))

// ---------------------------------------------------------------------------
// K0: prep — blocks [0,64): transpose W into g_Wt; rest: zero deg;
//     block 64 also: dtype detect + zero Z.
// ---------------------------------------------------------------------------
__global__ void prep_kernel(const float* __restrict__ W,
                            const unsigned int* __restrict__ ew, int nNodes)
{
    int b = blockIdx.x, t = threadIdx.x;
    if (b < 64) {
        int i = b * 256 + t;            // i < 16384
        int c = i >> 7, k = i & 127;
        g_Wt[k * HF + c] = W[i];
    } else {
        int i = (b - 64) * 256 + t;
        if (i < nNodes) g_deg[i] = 0;
        if (b == 64) {
            if (t < HEADS) g_Z[t] = 0.0f;
            if (t == 0) {
                int is64 = 1;
                for (int j = 0; j < 256; j++)
                    if (ew[2 * j + 1] != 0u) { is64 = 0; break; }
                g_is64 = is64;
            }
        }
    }
}

// ---------------------------------------------------------------------------
// K1: GEMM h = x @ W^T on packed f32x2 FFMA2 + fused attention epilogue.
// Block: 256 thr = 32 nodes; warp: 4 nodes; lane: cols [4*lane, 4*lane+4).
// x duplicated (v,v) in smem as 8B words; W rows read as ulonglong2 pairs.
// Epilogue: leaky-relu att dots, 8-lane butterfly, es/ed/Z-self,
// p = es*h stored fp16.
// ---------------------------------------------------------------------------
__global__ void __launch_bounds__(256)
gemm_fused_kernel(const float* __restrict__ x, const float* __restrict__ att,
                  int nNodes)
{
    __shared__ ull xs[32 * 128];     // 32 KB, (v,v) pairs
    __shared__ float zsm[HEADS];
    int tid = threadIdx.x;
    if (tid < HEADS) zsm[tid] = 0.0f;

    int base = blockIdx.x * 32;
    #pragma unroll
    for (int i = tid; i < 32 * 128; i += 256) {
        int n = base + (i >> 7);
        float v = (n < nNodes) ? x[n * IN_F + (i & 127)] : 0.0f;
        unsigned int bits = __float_as_uint(v);
        xs[i] = (ull)bits | ((ull)bits << 32);
    }
    __syncthreads();

    int warp = tid >> 5, lane = tid & 31;
    const ull* xr = xs + warp * 4 * 128;
    const ulonglong2* wt2 = (const ulonglong2*)g_Wt;  // row = 32 x 16B

    ull acc2[4][2];
    #pragma unroll
    for (int i = 0; i < 4; i++) { acc2[i][0] = 0ull; acc2[i][1] = 0ull; }

    #pragma unroll 4
    for (int k = 0; k < 128; k++) {
        ulonglong2 w2 = wt2[k * 32 + lane];   // LDG.128, L1-hot (64KB)
        #pragma unroll
        for (int i = 0; i < 4; i++) {
            ull xv = xr[i * 128 + k];         // LDS.64 of (v,v)
            FFMA2(acc2[i][0], xv, w2.x);      // cols 4l, 4l+1
            FFMA2(acc2[i][1], xv, w2.y);      // cols 4l+2, 4l+3
        }
    }

    int head = lane >> 3;
    int cb = (lane & 7) * 4;
    float as[4], ad[4];
    #pragma unroll
    for (int q = 0; q < 4; q++) {
        as[q] = att[head * 64 + cb + q];
        ad[q] = att[head * 64 + 32 + cb + q];
    }

    float zloc = 0.0f;
    #pragma unroll
    for (int i = 0; i < 4; i++) {
        float2 f0 = *(float2*)&acc2[i][0];
        float2 f1 = *(float2*)&acc2[i][1];
        float a0 = f0.x, a1 = f0.y, a2 = f1.x, a3 = f1.y;

        float pa = 0.0f, pd = 0.0f;
        {
            float v0 = a0, v1 = a1, v2 = a2, v3 = a3;
            float l0 = v0 > 0.f ? v0 : NEG_SLOPE * v0;
            float l1 = v1 > 0.f ? v1 : NEG_SLOPE * v1;
            float l2 = v2 > 0.f ? v2 : NEG_SLOPE * v2;
            float l3 = v3 > 0.f ? v3 : NEG_SLOPE * v3;
            pa = l0 * as[0] + l1 * as[1] + l2 * as[2] + l3 * as[3];
            pd = l0 * ad[0] + l1 * ad[1] + l2 * ad[2] + l3 * ad[3];
        }
        #pragma unroll
        for (int off = 1; off < 8; off <<= 1) {
            pa += __shfl_xor_sync(0xffffffffu, pa, off);
            pd += __shfl_xor_sync(0xffffffffu, pd, off);
        }
        float es = expf(pa), ed = expf(pd);
        int n = base + warp * 4 + i;
        if (n < nNodes) {
            if ((lane & 7) == 0) {
                g_es[n * HEADS + head] = es;
                g_ed[n * HEADS + head] = ed;
                zloc += es * ed;              // self-loop Z term
            }
            __half2 p01 = __floats2half2_rn(es * a0, es * a1);
            __half2 p23 = __floats2half2_rn(es * a2, es * a3);
            uint2 pu = make_uint2(*(unsigned int*)&p01, *(unsigned int*)&p23);
            *(uint2*)(g_p + n * HF + lane * 4) = pu;   // 8B, coalesced 256B/warp
        }
    }
    if ((lane & 7) == 0) atomicAdd(&zsm[head], zloc);
    __syncthreads();
    if (tid < HEADS) atomicAdd(&g_Z[tid], zsm[tid]);
}

// ---------------------------------------------------------------------------
// edge index loader (int64 or int32, uniform branch)
// ---------------------------------------------------------------------------
__device__ __forceinline__ void load_edge(const void* ei, int e, int nEdges,
                                          int is64, int& s, int& d)
{
    if (is64) {
        const long long* e64 = (const long long*)ei;
        s = (int)e64[e];
        d = (int)e64[e + nEdges];
    } else {
        const int* e32 = (const int*)ei;
        s = e32[e];
        d = e32[e + nEdges];
    }
}

// ---------------------------------------------------------------------------
// K2: histogram + per-edge rank + Z-edge. 4 edges per thread (MLP).
// ---------------------------------------------------------------------------
__global__ void __launch_bounds__(256)
histz_kernel(const void* __restrict__ ei, int nEdges, int nNodes)
{
    __shared__ float zsm[HEADS];
    int tid = threadIdx.x;
    if (tid < HEADS) zsm[tid] = 0.0f;
    __syncthreads();

    const int is64 = g_is64;
    int base = (blockIdx.x * 256 + tid) * 4;

    int s[4], d[4];
    bool v[4];
    float4 es4[4], ed4[4];

    #pragma unroll
    for (int q = 0; q < 4; q++) {
        int e = base + q;
        v[q] = (e < nEdges);
        if (v[q]) {
            load_edge(ei, e, nEdges, is64, s[q], d[q]);
            v[q] = ((unsigned)s[q] < (unsigned)nNodes) &&
                   ((unsigned)d[q] < (unsigned)nNodes);
        }
    }
    #pragma unroll
    for (int q = 0; q < 4; q++) {
        if (v[q]) {
            es4[q] = *(const float4*)(g_es + s[q] * HEADS);
            ed4[q] = *(const float4*)(g_ed + d[q] * HEADS);
        }
    }

    float z0 = 0.f, z1 = 0.f, z2 = 0.f, z3 = 0.f;
    #pragma unroll
    for (int q = 0; q < 4; q++) {
        if (v[q]) {
            int r = atomicAdd(&g_deg[d[q]], 1);
            g_rank[base + q] = r;
            z0 += es4[q].x * ed4[q].x;
            z1 += es4[q].y * ed4[q].y;
            z2 += es4[q].z * ed4[q].z;
            z3 += es4[q].w * ed4[q].w;
        }
    }
    #pragma unroll
    for (int off = 16; off; off >>= 1) {
        z0 += __shfl_xor_sync(0xffffffffu, z0, off);
        z1 += __shfl_xor_sync(0xffffffffu, z1, off);
        z2 += __shfl_xor_sync(0xffffffffu, z2, off);
        z3 += __shfl_xor_sync(0xffffffffu, z3, off);
    }
    if ((tid & 31) == 0) {
        atomicAdd(&zsm[0], z0);
        atomicAdd(&zsm[1], z1);
        atomicAdd(&zsm[2], z2);
        atomicAdd(&zsm[3], z3);
    }
    __syncthreads();
    if (tid < HEADS) atomicAdd(&g_Z[tid], zsm[tid]);
}

// ---------------------------------------------------------------------------
// K3a: per-chunk (1024 elems) sums of g_deg.
// ---------------------------------------------------------------------------
__global__ void scan1_kernel(int nNodes)
{
    int t = threadIdx.x, b = blockIdx.x;
    int i0 = b * 1024 + t * 4;
    int sv = 0;
    #pragma unroll
    for (int q = 0; q < 4; q++)
        if (i0 + q < nNodes) sv += g_deg[i0 + q];
    #pragma unroll
    for (int off = 16; off; off >>= 1)
        sv += __shfl_xor_sync(0xffffffffu, sv, off);
    __shared__ int wsum[8];
    if ((t & 31) == 0) wsum[t >> 5] = sv;
    __syncthreads();
    if (t == 0) {
        int tot = 0;
        #pragma unroll
        for (int w = 0; w < 8; w++) tot += wsum[w];
        g_bsum[b] = tot;
    }
}

// ---------------------------------------------------------------------------
// K3b: exclusive scan -> g_off ; block 0 also total + invZ.
// ---------------------------------------------------------------------------
__global__ void scan3_kernel(int nChunks, int nNodes)
{
    __shared__ int bs[64];
    __shared__ int wsum[8];
    int t = threadIdx.x, b = blockIdx.x;
    int lane = t & 31, warp = t >> 5;

    if (t < 64) bs[t] = (t < nChunks) ? g_bsum[t] : 0;
    __syncthreads();
    if (t == 0) {
        int r = 0;
        for (int i = 0; i < nChunks; i++) { int v = bs[i]; bs[i] = r; r += v; }
        if (b == 0) g_off[nNodes] = r;
    }
    if (b == 0 && t >= 32 && t < 32 + HEADS)
        g_invZ[t - 32] = 1.0f / g_Z[t - 32];
    __syncthreads();

    int i0 = b * 1024 + t * 4;
    int v[4];
    #pragma unroll
    for (int q = 0; q < 4; q++)
        v[q] = (i0 + q < nNodes) ? g_deg[i0 + q] : 0;
    int ts = v[0] + v[1] + v[2] + v[3];

    int xsc = ts;
    #pragma unroll
    for (int off = 1; off < 32; off <<= 1) {
        int y = __shfl_up_sync(0xffffffffu, xsc, off);
        if (lane >= off) xsc += y;
    }
    if (lane == 31) wsum[warp] = xsc;
    __syncthreads();
    if (t == 0) {
        int r = 0;
        #pragma unroll
        for (int w = 0; w < 8; w++) { int tv = wsum[w]; wsum[w] = r; r += tv; }
    }
    __syncthreads();
    int run = bs[b] + wsum[warp] + (xsc - ts);
    #pragma unroll
    for (int q = 0; q < 4; q++) {
        if (i0 + q < nNodes) {
            g_off[i0 + q] = run;
            run += v[q];
        }
    }
}

// ---------------------------------------------------------------------------
// K4: scatter — atomic-free: p = off[d] + rank[e]. 4 edges/thread.
// ---------------------------------------------------------------------------
__global__ void __launch_bounds__(256)
scatter_kernel(const void* __restrict__ ei, int nEdges, int nNodes)
{
    const int is64 = g_is64;
    int base = (blockIdx.x * 256 + threadIdx.x) * 4;
    #pragma unroll
    for (int q = 0; q < 4; q++) {
        int e = base + q;
        if (e >= nEdges) break;
        int s, d;
        load_edge(ei, e, nEdges, is64, s, d);
        if ((unsigned)s < (unsigned)nNodes && (unsigned)d < (unsigned)nNodes) {
            int p = g_off[d] + g_rank[e];
            if ((unsigned)p < (unsigned)MAX_EDGES) g_srcidx[p] = s;
        }
    }
}

// ---------------------------------------------------------------------------
// K5: edge accumulate (fp16 gather, fp32 acc) + fused final scale/bias.
// Warp per node. out[n] = (p[n] + sum p[s]) * ed[n]*invZ + bias
// ---------------------------------------------------------------------------
__global__ void __launch_bounds__(256)
edgeacc_kernel(float* __restrict__ out, const float* __restrict__ bias,
               int nNodes)
{
    int tid = threadIdx.x;
    int lane = tid & 31;
    int head = lane >> 3;
    int n = (blockIdx.x * 256 + tid) >> 5;
    if (n >= nNodes) return;

    int o0 = g_off[n], o1 = g_off[n + 1];
    float4 b4 = *(const float4*)(bias + lane * 4);
    float sc = g_ed[n * HEADS + head] * g_invZ[head];

    // self term: p[n] already = es[n]*h[n]
    uint2 su = *(const uint2*)(g_p + n * HF + lane * 4);
    float2 s0 = __half22float2(*(__half2*)&su.x);
    float2 s1 = __half22float2(*(__half2*)&su.y);
    float4 acc = make_float4(s0.x, s0.y, s1.x, s1.y);

    if (o0 < o1) {
        int s = g_srcidx[o0];
        for (int j = o0; j < o1; j++) {
            int s_next = (j + 1 < o1) ? g_srcidx[j + 1] : 0;
            uint2 pu = *(const uint2*)(g_p + s * HF + lane * 4); // 8B/lane
            float2 f0 = __half22float2(*(__half2*)&pu.x);
            float2 f1 = __half22float2(*(__half2*)&pu.y);
            acc.x += f0.x;
            acc.y += f0.y;
            acc.z += f1.x;
            acc.w += f1.y;
            s = s_next;
        }
    }
    *(float4*)(out + n * HF + lane * 4) =
        make_float4(acc.x * sc + b4.x, acc.y * sc + b4.y,
                    acc.z * sc + b4.z, acc.w * sc + b4.w);
}

// ---------------------------------------------------------------------------
// Host: identify inputs by SIZE RANK (order-proof):
//   x (6.4M) > edge_index (1.6M) > W (16384) > att (256) > bias (128)
// ---------------------------------------------------------------------------
extern "C" void kernel_launch(void* const* d_in, const int* in_sizes, int n_in,
                              void* d_out, int out_size)
{
    int idx[16];
    for (int i = 0; i < n_in && i < 16; i++) idx[i] = i;
    for (int a = 0; a < n_in; a++)
        for (int b = a + 1; b < n_in; b++)
            if (in_sizes[idx[b]] > in_sizes[idx[a]]) {
                int t = idx[a]; idx[a] = idx[b]; idx[b] = t;
            }

    const float* x    = (const float*)d_in[idx[0]];
    const void*  ei   = d_in[idx[1]];
    const float* W    = (const float*)d_in[idx[2]];
    const float* att  = (const float*)d_in[idx[3]];
    const float* bias = (const float*)d_in[idx[4]];
    float* out = (float*)d_out;

    int nNodes = in_sizes[idx[0]] / IN_F;
    int nEdges = in_sizes[idx[1]] / 2;
    if (nNodes > MAX_NODES) nNodes = MAX_NODES;
    if (nEdges > MAX_EDGES) nEdges = MAX_EDGES;

    int zero_blocks = (nNodes + 255) / 256;
    prep_kernel<<<64 + zero_blocks, 256>>>(W, (const unsigned int*)ei, nNodes);

    int gemm_blocks = (nNodes + 31) / 32;
    gemm_fused_kernel<<<gemm_blocks, 256>>>(x, att, nNodes);

    int e4blocks = (nEdges + 1023) / 1024;
    histz_kernel<<<e4blocks, 256>>>(ei, nEdges, nNodes);

    int nChunks = (nNodes + 1023) / 1024;
    scan1_kernel<<<nChunks, 256>>>(nNodes);
    scan3_kernel<<<nChunks, 256>>>(nChunks, nNodes);

    scatter_kernel<<<e4blocks, 256>>>(ei, nEdges, nNodes);

    int ablocks = (nNodes * 32 + 255) / 256;
    edgeacc_kernel<<<ablocks, 256>>>(out, bias, nNodes);
}

// round 16
// speedup vs baseline: 1.1786x; 1.1786x over previous
#include <cuda_runtime.h>
#include <cuda_fp16.h>
#include <cuda_bf16.h>

// ---------------------------------------------------------------------------
// GATv2-like layer, factorized global softmax + CSR edge aggregation.
//   h = x @ W^T ; scores separable => w[e,h] = es[src,h]*ed[dst,h]/Z_h
//   p[n] = es[n]*h[n]  (fp16 pre-scaled gather payload; only consumer of h)
//   out[d] = ed[d]*invZ * ( p[d] + sum_{in-edges} p[s] ) + bias
// Pipeline (7 launches):
//   prep -> gemm_fused (R12-proven FFMA GEMM; epilogue stores p fp16)
//   -> histz -> scan1 -> scan3(+invZ) -> scatter -> edgeacc(+scale+bias)
// ---------------------------------------------------------------------------

#define IN_F      128
#define HEADS     4
#define OUT_F     32
#define HF        128
#define NEG_SLOPE 0.2f
#define MAX_NODES 50000
#define MAX_EDGES 800000

__device__ __half g_p[MAX_NODES * HF];       // 12.8 MB fp16 payload
__device__ float  g_Wt[IN_F * HF];           // W^T, k-major
__device__ float  g_es[MAX_NODES * HEADS];
__device__ float  g_ed[MAX_NODES * HEADS];
__device__ float  g_Z[HEADS];
__device__ float  g_invZ[HEADS];
__device__ int    g_is64;

__device__ int    g_deg[MAX_NODES];
__device__ int    g_off[MAX_NODES + 1];
__device__ int    g_bsum[64];
__device__ int    g_rank[MAX_EDGES];
__device__ int    g_srcidx[MAX_EDGES];

// ---------------------------------------------------------------------------
// K0: prep — blocks [0,64): transpose W into g_Wt; rest: zero deg;
//     block 64 also: dtype detect + zero Z.
// ---------------------------------------------------------------------------
__global__ void prep_kernel(const float* __restrict__ W,
                            const unsigned int* __restrict__ ew, int nNodes)
{
    int b = blockIdx.x, t = threadIdx.x;
    if (b < 64) {
        int i = b * 256 + t;            // i < 16384
        int c = i >> 7, k = i & 127;
        g_Wt[k * HF + c] = W[i];
    } else {
        int i = (b - 64) * 256 + t;
        if (i < nNodes) g_deg[i] = 0;
        if (b == 64) {
            if (t < HEADS) g_Z[t] = 0.0f;
            if (t == 0) {
                int is64 = 1;
                for (int j = 0; j < 256; j++)
                    if (ew[2 * j + 1] != 0u) { is64 = 0; break; }
                g_is64 = is64;
            }
        }
    }
}

// ---------------------------------------------------------------------------
// K1: GEMM h = x @ W^T (R12-proven shape) + fused attention epilogue.
// Block: 256 thr = 64 nodes; warp: 8 nodes; lane: col quad 4*lane.
// Epilogue: leaky-relu att dots, 8-lane butterfly, es/ed/Z-self,
// p = es*h stored fp16 (uint2, 8B/lane — cheaper than R12's float4 store).
// ---------------------------------------------------------------------------
__global__ void __launch_bounds__(256)
gemm_fused_kernel(const float* __restrict__ x, const float* __restrict__ att,
                  int nNodes)
{
    __shared__ float xs[64 * 128];   // 32 KB
    __shared__ float zsm[HEADS];
    int tid = threadIdx.x;
    if (tid < HEADS) zsm[tid] = 0.0f;

    int base = blockIdx.x * 64;
    #pragma unroll
    for (int i = tid; i < 64 * 128; i += 256) {
        int n = base + (i >> 7);
        xs[i] = (n < nNodes) ? x[n * IN_F + (i & 127)] : 0.0f;
    }
    __syncthreads();

    int warp = tid >> 5, lane = tid & 31;
    const float* xr = xs + warp * 8 * 128;
    const float4* wt4 = (const float4*)g_Wt;

    float acc[8][4];
    #pragma unroll
    for (int i = 0; i < 8; i++)
        #pragma unroll
        for (int q = 0; q < 4; q++) acc[i][q] = 0.0f;

    #pragma unroll 4
    for (int k = 0; k < 128; k++) {
        float4 w4 = wt4[k * 32 + lane];       // L1-hot LDG.128
        #pragma unroll
        for (int i = 0; i < 8; i++) {
            float xv = xr[i * 128 + k];       // LDS broadcast
            acc[i][0] += xv * w4.x;
            acc[i][1] += xv * w4.y;
            acc[i][2] += xv * w4.z;
            acc[i][3] += xv * w4.w;
        }
    }

    int head = lane >> 3;
    int cb = (lane & 7) * 4;
    float as[4], ad[4];
    #pragma unroll
    for (int q = 0; q < 4; q++) {
        as[q] = att[head * 64 + cb + q];
        ad[q] = att[head * 64 + 32 + cb + q];
    }

    float zloc = 0.0f;
    #pragma unroll
    for (int i = 0; i < 8; i++) {
        float pa = 0.0f, pd = 0.0f;
        #pragma unroll
        for (int q = 0; q < 4; q++) {
            float v = acc[i][q];
            float lr = v > 0.0f ? v : NEG_SLOPE * v;
            pa += lr * as[q];
            pd += lr * ad[q];
        }
        #pragma unroll
        for (int off = 1; off < 8; off <<= 1) {
            pa += __shfl_xor_sync(0xffffffffu, pa, off);
            pd += __shfl_xor_sync(0xffffffffu, pd, off);
        }
        float es = expf(pa), ed = expf(pd);
        int n = base + warp * 8 + i;
        if (n < nNodes) {
            if ((lane & 7) == 0) {
                g_es[n * HEADS + head] = es;
                g_ed[n * HEADS + head] = ed;
                zloc += es * ed;              // self-loop Z term
            }
            __half2 p01 = __floats2half2_rn(es * acc[i][0], es * acc[i][1]);
            __half2 p23 = __floats2half2_rn(es * acc[i][2], es * acc[i][3]);
            uint2 pu = make_uint2(*(unsigned int*)&p01, *(unsigned int*)&p23);
            *(uint2*)(g_p + n * HF + lane * 4) = pu;  // 8B, coalesced 256B/warp
        }
    }
    if ((lane & 7) == 0) atomicAdd(&zsm[head], zloc);
    __syncthreads();
    if (tid < HEADS) atomicAdd(&g_Z[tid], zsm[tid]);
}

// ---------------------------------------------------------------------------
// edge index loader (int64 or int32, uniform branch)
// ---------------------------------------------------------------------------
__device__ __forceinline__ void load_edge(const void* ei, int e, int nEdges,
                                          int is64, int& s, int& d)
{
    if (is64) {
        const long long* e64 = (const long long*)ei;
        s = (int)e64[e];
        d = (int)e64[e + nEdges];
    } else {
        const int* e32 = (const int*)ei;
        s = e32[e];
        d = e32[e + nEdges];
    }
}

// ---------------------------------------------------------------------------
// K2: histogram + per-edge rank + Z-edge. 4 edges per thread (MLP).
// ---------------------------------------------------------------------------
__global__ void __launch_bounds__(256)
histz_kernel(const void* __restrict__ ei, int nEdges, int nNodes)
{
    __shared__ float zsm[HEADS];
    int tid = threadIdx.x;
    if (tid < HEADS) zsm[tid] = 0.0f;
    __syncthreads();

    const int is64 = g_is64;
    int base = (blockIdx.x * 256 + tid) * 4;

    int s[4], d[4];
    bool v[4];
    float4 es4[4], ed4[4];

    #pragma unroll
    for (int q = 0; q < 4; q++) {
        int e = base + q;
        v[q] = (e < nEdges);
        if (v[q]) {
            load_edge(ei, e, nEdges, is64, s[q], d[q]);
            v[q] = ((unsigned)s[q] < (unsigned)nNodes) &&
                   ((unsigned)d[q] < (unsigned)nNodes);
        }
    }
    #pragma unroll
    for (int q = 0; q < 4; q++) {
        if (v[q]) {
            es4[q] = *(const float4*)(g_es + s[q] * HEADS);
            ed4[q] = *(const float4*)(g_ed + d[q] * HEADS);
        }
    }

    float z0 = 0.f, z1 = 0.f, z2 = 0.f, z3 = 0.f;
    #pragma unroll
    for (int q = 0; q < 4; q++) {
        if (v[q]) {
            int r = atomicAdd(&g_deg[d[q]], 1);
            g_rank[base + q] = r;
            z0 += es4[q].x * ed4[q].x;
            z1 += es4[q].y * ed4[q].y;
            z2 += es4[q].z * ed4[q].z;
            z3 += es4[q].w * ed4[q].w;
        }
    }
    #pragma unroll
    for (int off = 16; off; off >>= 1) {
        z0 += __shfl_xor_sync(0xffffffffu, z0, off);
        z1 += __shfl_xor_sync(0xffffffffu, z1, off);
        z2 += __shfl_xor_sync(0xffffffffu, z2, off);
        z3 += __shfl_xor_sync(0xffffffffu, z3, off);
    }
    if ((tid & 31) == 0) {
        atomicAdd(&zsm[0], z0);
        atomicAdd(&zsm[1], z1);
        atomicAdd(&zsm[2], z2);
        atomicAdd(&zsm[3], z3);
    }
    __syncthreads();
    if (tid < HEADS) atomicAdd(&g_Z[tid], zsm[tid]);
}

// ---------------------------------------------------------------------------
// K3a: per-chunk (1024 elems) sums of g_deg.
// ---------------------------------------------------------------------------
__global__ void scan1_kernel(int nNodes)
{
    int t = threadIdx.x, b = blockIdx.x;
    int i0 = b * 1024 + t * 4;
    int sv = 0;
    #pragma unroll
    for (int q = 0; q < 4; q++)
        if (i0 + q < nNodes) sv += g_deg[i0 + q];
    #pragma unroll
    for (int off = 16; off; off >>= 1)
        sv += __shfl_xor_sync(0xffffffffu, sv, off);
    __shared__ int wsum[8];
    if ((t & 31) == 0) wsum[t >> 5] = sv;
    __syncthreads();
    if (t == 0) {
        int tot = 0;
        #pragma unroll
        for (int w = 0; w < 8; w++) tot += wsum[w];
        g_bsum[b] = tot;
    }
}

// ---------------------------------------------------------------------------
// K3b: exclusive scan -> g_off ; block 0 also total + invZ.
// ---------------------------------------------------------------------------
__global__ void scan3_kernel(int nChunks, int nNodes)
{
    __shared__ int bs[64];
    __shared__ int wsum[8];
    int t = threadIdx.x, b = blockIdx.x;
    int lane = t & 31, warp = t >> 5;

    if (t < 64) bs[t] = (t < nChunks) ? g_bsum[t] : 0;
    __syncthreads();
    if (t == 0) {
        int r = 0;
        for (int i = 0; i < nChunks; i++) { int v = bs[i]; bs[i] = r; r += v; }
        if (b == 0) g_off[nNodes] = r;
    }
    if (b == 0 && t >= 32 && t < 32 + HEADS)
        g_invZ[t - 32] = 1.0f / g_Z[t - 32];
    __syncthreads();

    int i0 = b * 1024 + t * 4;
    int v[4];
    #pragma unroll
    for (int q = 0; q < 4; q++)
        v[q] = (i0 + q < nNodes) ? g_deg[i0 + q] : 0;
    int ts = v[0] + v[1] + v[2] + v[3];

    int xsc = ts;
    #pragma unroll
    for (int off = 1; off < 32; off <<= 1) {
        int y = __shfl_up_sync(0xffffffffu, xsc, off);
        if (lane >= off) xsc += y;
    }
    if (lane == 31) wsum[warp] = xsc;
    __syncthreads();
    if (t == 0) {
        int r = 0;
        #pragma unroll
        for (int w = 0; w < 8; w++) { int tv = wsum[w]; wsum[w] = r; r += tv; }
    }
    __syncthreads();
    int run = bs[b] + wsum[warp] + (xsc - ts);
    #pragma unroll
    for (int q = 0; q < 4; q++) {
        if (i0 + q < nNodes) {
            g_off[i0 + q] = run;
            run += v[q];
        }
    }
}

// ---------------------------------------------------------------------------
// K4: scatter — atomic-free: p = off[d] + rank[e]. 4 edges/thread.
// ---------------------------------------------------------------------------
__global__ void __launch_bounds__(256)
scatter_kernel(const void* __restrict__ ei, int nEdges, int nNodes)
{
    const int is64 = g_is64;
    int base = (blockIdx.x * 256 + threadIdx.x) * 4;
    #pragma unroll
    for (int q = 0; q < 4; q++) {
        int e = base + q;
        if (e >= nEdges) break;
        int s, d;
        load_edge(ei, e, nEdges, is64, s, d);
        if ((unsigned)s < (unsigned)nNodes && (unsigned)d < (unsigned)nNodes) {
            int p = g_off[d] + g_rank[e];
            if ((unsigned)p < (unsigned)MAX_EDGES) g_srcidx[p] = s;
        }
    }
}

// ---------------------------------------------------------------------------
// K5: edge accumulate (fp16 __ldg gather, fp32 acc) + fused scale/bias.
// Warp per node. out[n] = (p[n] + sum p[s]) * ed[n]*invZ + bias
// ---------------------------------------------------------------------------
__global__ void __launch_bounds__(256)
edgeacc_kernel(float* __restrict__ out, const float* __restrict__ bias,
               int nNodes)
{
    int tid = threadIdx.x;
    int lane = tid & 31;
    int head = lane >> 3;
    int n = (blockIdx.x * 256 + tid) >> 5;
    if (n >= nNodes) return;

    int o0 = g_off[n], o1 = g_off[n + 1];
    float4 b4 = *(const float4*)(bias + lane * 4);
    float sc = g_ed[n * HEADS + head] * g_invZ[head];

    // self term: p[n] = es[n]*h[n]
    uint2 su = *(const uint2*)(g_p + n * HF + lane * 4);
    float2 s0 = __half22float2(*(__half2*)&su.x);
    float2 s1 = __half22float2(*(__half2*)&su.y);
    float4 acc = make_float4(s0.x, s0.y, s1.x, s1.y);

    if (o0 < o1) {
        int s = __ldg(g_srcidx + o0);
        for (int j = o0; j < o1; j++) {
            int s_next = (j + 1 < o1) ? __ldg(g_srcidx + j + 1) : 0;
            uint2 pu = __ldg((const uint2*)(g_p + s * HF + lane * 4)); // 8B/lane
            float2 f0 = __half22float2(*(__half2*)&pu.x);
            float2 f1 = __half22float2(*(__half2*)&pu.y);
            acc.x += f0.x;
            acc.y += f0.y;
            acc.z += f1.x;
            acc.w += f1.y;
            s = s_next;
        }
    }
    *(float4*)(out + n * HF + lane * 4) =
        make_float4(acc.x * sc + b4.x, acc.y * sc + b4.y,
                    acc.z * sc + b4.z, acc.w * sc + b4.w);
}

// ---------------------------------------------------------------------------
// Host: identify inputs by SIZE RANK (order-proof):
//   x (6.4M) > edge_index (1.6M) > W (16384) > att (256) > bias (128)
// ---------------------------------------------------------------------------
extern "C" void kernel_launch(void* const* d_in, const int* in_sizes, int n_in,
                              void* d_out, int out_size)
{
    int idx[16];
    for (int i = 0; i < n_in && i < 16; i++) idx[i] = i;
    for (int a = 0; a < n_in; a++)
        for (int b = a + 1; b < n_in; b++)
            if (in_sizes[idx[b]] > in_sizes[idx[a]]) {
                int t = idx[a]; idx[a] = idx[b]; idx[b] = t;
            }

    const float* x    = (const float*)d_in[idx[0]];
    const void*  ei   = d_in[idx[1]];
    const float* W    = (const float*)d_in[idx[2]];
    const float* att  = (const float*)d_in[idx[3]];
    const float* bias = (const float*)d_in[idx[4]];
    float* out = (float*)d_out;

    int nNodes = in_sizes[idx[0]] / IN_F;
    int nEdges = in_sizes[idx[1]] / 2;
    if (nNodes > MAX_NODES) nNodes = MAX_NODES;
    if (nEdges > MAX_EDGES) nEdges = MAX_EDGES;

    int zero_blocks = (nNodes + 255) / 256;
    prep_kernel<<<64 + zero_blocks, 256>>>(W, (const unsigned int*)ei, nNodes);

    int gemm_blocks = (nNodes + 63) / 64;
    gemm_fused_kernel<<<gemm_blocks, 256>>>(x, att, nNodes);

    int e4blocks = (nEdges + 1023) / 1024;
    histz_kernel<<<e4blocks, 256>>>(ei, nEdges, nNodes);

    int nChunks = (nNodes + 1023) / 1024;
    scan1_kernel<<<nChunks, 256>>>(nNodes);
    scan3_kernel<<<nChunks, 256>>>(nChunks, nNodes);

    scatter_kernel<<<e4blocks, 256>>>(ei, nEdges, nNodes);

    int ablocks = (nNodes * 32 + 255) / 256;
    edgeacc_kernel<<<ablocks, 256>>>(out, bias, nNodes);
}